// round 10
// baseline (speedup 1.0000x reference)
#include <cuda_runtime.h>

// -------- Instant-NGP constants --------
#define NLEV 16
#define TSZ  (1u << 19)
#define HMASK (TSZ - 1u)
#define P2 2654435761u
#define P3 805459861u

#define PMAX 393216                 // 2048 * 192 (fixed problem shape)

// scratch: feats laid out as [chunk 0..7][point][float4] — coalesced both ways
__device__ float4 g_feats[8 * PMAX];

// ---- weights in the constant bank: immediate-addressed uniform loads ----
#define OFF_DW1 0      // 32*64 = 2048
#define OFF_DB1 2048   // 64
#define OFF_DW2 2112   // 64*16 = 1024
#define OFF_DB2 3136   // 16
#define OFF_CW1 3152   // 43*64 = 2752
#define OFF_CB1 5904   // 64
#define OFF_CW2 5968   // 64*64 = 4096
#define OFF_CB2 10064  // 64
#define OFF_CW3 10128  // 64*3 = 192
#define OFF_CB3 10320  // 3
#define W_PAD   10324  // 41,296 bytes < 64KB constant bank

__constant__ __align__(16) float cWt[W_PAD];

// ---- packed f32x2 helpers (sm_103a FFMA2 — PTX-only) ----
typedef unsigned long long u64t;
__device__ __forceinline__ void ffma2(u64t& d, u64t a2, u64t b2) {
    asm("fma.rn.f32x2 %0, %1, %2, %0;" : "+l"(d) : "l"(a2), "l"(b2));
}
__device__ __forceinline__ u64t dup2(float a) {
    u64t r; unsigned ai = __float_as_uint(a);
    asm("mov.b64 %0, {%1, %1};" : "=l"(r) : "r"(ai));
    return r;
}
__device__ __forceinline__ void unpack2(u64t v, float& lo, float& hi) {
    unsigned l, h;
    asm("mov.b64 {%0, %1}, %2;" : "=r"(l), "=r"(h) : "l"(v));
    lo = __uint_as_float(l); hi = __uint_as_float(h);
}

// ============================ Kernel A: hash gather ============================
__global__ void __launch_bounds__(256)
ngp_gather_kernel(const float* __restrict__ x,
                  const float* __restrict__ tables, int P)
{
    const int p = blockIdx.x * 256 + threadIdx.x;
    if (p >= P) return;

    const float xf0 = x[3 * p + 0] + 0.5f;
    const float xf1 = x[3 * p + 1] + 0.5f;
    const float xf2 = x[3 * p + 2] + 0.5f;
    const bool inside = (xf0 > 0.f) & (xf0 < 1.f) &
                        (xf1 > 0.f) & (xf1 < 1.f) &
                        (xf2 > 0.f) & (xf2 < 1.f);
    if (!inside) {
        const float4 z = make_float4(0.f, 0.f, 0.f, 0.f);
#pragma unroll
        for (int c = 0; c < 8; c++) g_feats[c * PMAX + p] = z;
        return;
    }

    const float LVL[NLEV] = {16.f, 22.f, 30.f, 42.f, 58.f, 80.f, 111.f, 153.f,
                             212.f, 294.f, 406.f, 561.f, 776.f, 1072.f, 1482.f, 2048.f};
    const float2* __restrict__ tab2 = (const float2*)tables;

    float prevx = 0.f, prevy = 0.f;
#pragma unroll
    for (int l = 0; l < NLEV; l++) {
        const float R = LVL[l];
        const float px = xf0 * R, py = xf1 * R, pz = xf2 * R;
        const float fx = floorf(px), fy = floorf(py), fz = floorf(pz);
        const float frx = px - fx, fry = py - fy, frz = pz - fz;
        const unsigned ux0 = (unsigned)(int)fx;
        const unsigned ux1 = (unsigned)(int)ceilf(px);
        const unsigned uy0 = (unsigned)(int)fy        * P2;
        const unsigned uy1 = (unsigned)(int)ceilf(py) * P2;
        const unsigned uz0 = (unsigned)(int)fz        * P3;
        const unsigned uz1 = (unsigned)(int)ceilf(pz) * P3;
        const float wx0 = 1.f - frx, wy0 = 1.f - fry, wz0 = 1.f - frz;
        const float2* __restrict__ tl = tab2 + (size_t)l * TSZ;
        float ax = 0.f, ay = 0.f;
#pragma unroll
        for (int c = 0; c < 8; c++) {
            unsigned h = ((c & 1) ? ux1 : ux0) ^ ((c & 2) ? uy1 : uy0) ^
                         ((c & 4) ? uz1 : uz0);
            h &= HMASK;
            const float2 v = __ldg(&tl[h]);
            const float w = ((c & 1) ? frx : wx0) * ((c & 2) ? fry : wy0) *
                            ((c & 4) ? frz : wz0);
            ax = fmaf(w, v.x, ax);
            ay = fmaf(w, v.y, ay);
        }
        if (l & 1) {
            g_feats[(l >> 1) * PMAX + p] = make_float4(prevx, prevy, ax, ay);
        } else {
            prevx = ax; prevy = ay;
        }
    }
}

// ============================ Kernel B: half-split MLPs (top-level syncs) ============================
#define PTS_PER_BLOCK 64

// Phase 1: density layer 1, this half computes outputs [HALF*32, HALF*32+32)
template<int HALF>
__device__ __forceinline__ void phase_dl1(int p, int pl, float* __restrict__ sA)
{
    u64t acc2[16];
    {
        const u64t* __restrict__ b = (const u64t*)(cWt + OFF_DB1 + HALF * 32);
#pragma unroll
        for (int j = 0; j < 16; j++) acc2[j] = b[j];
    }
#pragma unroll
    for (int c = 0; c < 8; c++) {
        const float4 f = __ldg(&g_feats[c * PMAX + p]);
        const float fa[4] = {f.x, f.y, f.z, f.w};
#pragma unroll
        for (int i = 0; i < 4; i++) {
            const u64t a2 = dup2(fa[i]);
            const u64t* __restrict__ w =
                (const u64t*)(cWt + OFF_DW1 + (4 * c + i) * 64 + HALF * 32);
#pragma unroll
            for (int j = 0; j < 16; j++) ffma2(acc2[j], a2, w[j]);
        }
    }
#pragma unroll
    for (int j = 0; j < 16; j++) {
        float lo, hi; unpack2(acc2[j], lo, hi);
        sA[(HALF * 32 + 2 * j + 0) * PTS_PER_BLOCK + pl] = fmaxf(lo, 0.f);
        sA[(HALF * 32 + 2 * j + 1) * PTS_PER_BLOCK + pl] = fmaxf(hi, 0.f);
    }
}

// Phase 2: density layer 2, this half computes ls[HALF*8, HALF*8+8). Returns ls[0] (HALF==0).
template<int HALF>
__device__ __forceinline__ float phase_dl2(int pl, const float* __restrict__ sA,
                                           float* __restrict__ lsb)
{
    u64t lsa[4];
    {
        const u64t* __restrict__ b = (const u64t*)(cWt + OFF_DB2 + HALF * 8);
#pragma unroll
        for (int j = 0; j < 4; j++) lsa[j] = b[j];
    }
#pragma unroll
    for (int k = 0; k < 64; k++) {
        const u64t a2 = dup2(sA[k * PTS_PER_BLOCK + pl]);
        const u64t* __restrict__ w = (const u64t*)(cWt + OFF_DW2 + k * 16 + HALF * 8);
#pragma unroll
        for (int j = 0; j < 4; j++) ffma2(lsa[j], a2, w[j]);
    }
    float ls0 = 0.f;
#pragma unroll
    for (int j = 0; j < 4; j++) {
        float lo, hi; unpack2(lsa[j], lo, hi);
        if (HALF == 0 && j == 0) ls0 = lo;
        lsb[(HALF * 8 + 2 * j + 0) * PTS_PER_BLOCK + pl] = lo;
        lsb[(HALF * 8 + 2 * j + 1) * PTS_PER_BLOCK + pl] = hi;
    }
    return ls0;
}

// Phase 3: color layer 1; inputs = 16 ls (smem) + 27 pe (regs); outputs [HALF*32, +32)
template<int HALF>
__device__ __forceinline__ void phase_cl1(int pl, const float* __restrict__ pe,
                                          const float* __restrict__ lsb,
                                          float* __restrict__ sA)
{
    u64t acc2[16];
    {
        const u64t* __restrict__ b = (const u64t*)(cWt + OFF_CB1 + HALF * 32);
#pragma unroll
        for (int j = 0; j < 16; j++) acc2[j] = b[j];
    }
#pragma unroll
    for (int k = 0; k < 16; k++) {
        const u64t a2 = dup2(lsb[k * PTS_PER_BLOCK + pl]);
        const u64t* __restrict__ w = (const u64t*)(cWt + OFF_CW1 + k * 64 + HALF * 32);
#pragma unroll
        for (int j = 0; j < 16; j++) ffma2(acc2[j], a2, w[j]);
    }
#pragma unroll
    for (int k = 16; k < 43; k++) {
        const u64t a2 = dup2(pe[k - 16]);
        const u64t* __restrict__ w = (const u64t*)(cWt + OFF_CW1 + k * 64 + HALF * 32);
#pragma unroll
        for (int j = 0; j < 16; j++) ffma2(acc2[j], a2, w[j]);
    }
#pragma unroll
    for (int j = 0; j < 16; j++) {
        float lo, hi; unpack2(acc2[j], lo, hi);
        sA[(HALF * 32 + 2 * j + 0) * PTS_PER_BLOCK + pl] = fmaxf(lo, 0.f);
        sA[(HALF * 32 + 2 * j + 1) * PTS_PER_BLOCK + pl] = fmaxf(hi, 0.f);
    }
}

// Phase 4: color layer 2 (+ partial layer-3 logits over this half's 32 h2 values)
template<int HALF>
__device__ __forceinline__ void phase_cl23(int pl, const float* __restrict__ sA,
                                           float& c0, float& c1, float& c2)
{
    u64t acc2[16];
    {
        const u64t* __restrict__ b = (const u64t*)(cWt + OFF_CB2 + HALF * 32);
#pragma unroll
        for (int j = 0; j < 16; j++) acc2[j] = b[j];
    }
#pragma unroll
    for (int k = 0; k < 64; k++) {
        const u64t a2 = dup2(sA[k * PTS_PER_BLOCK + pl]);
        const u64t* __restrict__ w = (const u64t*)(cWt + OFF_CW2 + k * 64 + HALF * 32);
#pragma unroll
        for (int j = 0; j < 16; j++) ffma2(acc2[j], a2, w[j]);
    }
    c0 = (HALF == 0) ? cWt[OFF_CB3 + 0] : 0.f;
    c1 = (HALF == 0) ? cWt[OFF_CB3 + 1] : 0.f;
    c2 = (HALF == 0) ? cWt[OFF_CB3 + 2] : 0.f;
#pragma unroll
    for (int j = 0; j < 16; j++) {
        float lo, hi; unpack2(acc2[j], lo, hi);
        const float v0 = fmaxf(lo, 0.f);
        const float v1 = fmaxf(hi, 0.f);
        const int idx = HALF * 32 + 2 * j;
        c0 = fmaf(v0, cWt[OFF_CW3 + idx * 3 + 0], c0);
        c1 = fmaf(v0, cWt[OFF_CW3 + idx * 3 + 1], c1);
        c2 = fmaf(v0, cWt[OFF_CW3 + idx * 3 + 2], c2);
        c0 = fmaf(v1, cWt[OFF_CW3 + idx * 3 + 3], c0);
        c1 = fmaf(v1, cWt[OFF_CW3 + idx * 3 + 4], c1);
        c2 = fmaf(v1, cWt[OFF_CW3 + idx * 3 + 5], c2);
    }
}

__global__ void __launch_bounds__(128, 5)
ngp_mlp_kernel(const float* __restrict__ x,
               const float* __restrict__ rdir,
               float* __restrict__ out, int P)
{
    __shared__ float sA[64 * PTS_PER_BLOCK];    // 16 KB: activations, transposed
    __shared__ float lsb[16 * PTS_PER_BLOCK];   //  4 KB: log_sigma / partials

    const int tid  = threadIdx.x;
    const int warp = tid >> 5;
    const int lane = tid & 31;
    const int q    = warp >> 1;          // pair index 0..1
    const int half = warp & 1;           // output-half of this warp

    const int p  = blockIdx.x * PTS_PER_BLOCK + q * 32 + lane;  // grid exact: P%64==0
    const int pl = q * 32 + lane;

    // ---- mask ----
    const float xf0 = x[3 * p + 0] + 0.5f;
    const float xf1 = x[3 * p + 1] + 0.5f;
    const float xf2 = x[3 * p + 2] + 0.5f;
    const bool inside = (xf0 > 0.f) & (xf0 < 1.f) &
                        (xf1 > 0.f) & (xf1 < 1.f) &
                        (xf2 > 0.f) & (xf2 < 1.f);

    // ---- phase 1: density layer 1 ----
    if (half == 0) phase_dl1<0>(p, pl, sA);
    else           phase_dl1<1>(p, pl, sA);
    __syncthreads();

    // ---- phase 2: density layer 2 + direction PE ----
    float ls0;
    if (half == 0) ls0 = phase_dl2<0>(pl, sA, lsb);
    else           ls0 = phase_dl2<1>(pl, sA, lsb);

    float pe[27];
    {
        const float r0 = rdir[3 * p + 0];
        const float r1 = rdir[3 * p + 1];
        const float r2 = rdir[3 * p + 2];
        pe[0] = r0; pe[1] = r1; pe[2] = r2;
        const float rv[3] = {r0, r1, r2};
#pragma unroll
        for (int d = 0; d < 3; d++) {
#pragma unroll
            for (int l = 0; l < 4; l++) {
                float s, c;
                __sincosf(rv[d] * (6.283185307179586f * (float)(1 << l)), &s, &c);
                pe[3 + d * 8 + l]     = s;
                pe[3 + d * 8 + 4 + l] = c;
            }
        }
    }
    __syncthreads();

    // ---- phase 3: color layer 1 ----
    if (half == 0) phase_cl1<0>(pl, pe, lsb, sA);
    else           phase_cl1<1>(pl, pe, lsb, sA);
    __syncthreads();

    // ---- phase 4: color layers 2+3 partials ----
    float c0, c1, c2;
    if (half == 0) {
        phase_cl23<0>(pl, sA, c0, c1, c2);
    } else {
        phase_cl23<1>(pl, sA, c0, c1, c2);
        lsb[0 * PTS_PER_BLOCK + pl] = c0;
        lsb[1 * PTS_PER_BLOCK + pl] = c1;
        lsb[2 * PTS_PER_BLOCK + pl] = c2;
    }
    __syncthreads();

    // ---- phase 5: finalize (half 0 only) ----
    if (half == 0) {
        c0 += lsb[0 * PTS_PER_BLOCK + pl];
        c1 += lsb[1 * PTS_PER_BLOCK + pl];
        c2 += lsb[2 * PTS_PER_BLOCK + pl];
        float o0 = 1.f / (1.f + __expf(-c0));
        float o1 = 1.f / (1.f + __expf(-c1));
        float o2 = 1.f / (1.f + __expf(-c2));
        float sg = __expf(ls0);
        if (!inside) { o0 = 0.f; o1 = 0.f; o2 = 0.f; sg = 0.f; }
        out[3 * p + 0] = o0;
        out[3 * p + 1] = o1;
        out[3 * p + 2] = o2;
        out[3 * P + p] = sg;
    }
}

extern "C" void kernel_launch(void* const* d_in, const int* in_sizes, int n_in,
                              void* d_out, int out_size)
{
    (void)n_in; (void)out_size;
    const float* x      = (const float*)d_in[0];
    const float* rdir   = (const float*)d_in[1];
    const float* tables = (const float*)d_in[2];
    float* out = (float*)d_out;

    // weights -> constant bank (device-to-device async copies: graph-capturable)
    cudaMemcpyToSymbolAsync(cWt, d_in[3],  2048 * 4, OFF_DW1 * 4, cudaMemcpyDeviceToDevice);
    cudaMemcpyToSymbolAsync(cWt, d_in[4],    64 * 4, OFF_DB1 * 4, cudaMemcpyDeviceToDevice);
    cudaMemcpyToSymbolAsync(cWt, d_in[5],  1024 * 4, OFF_DW2 * 4, cudaMemcpyDeviceToDevice);
    cudaMemcpyToSymbolAsync(cWt, d_in[6],    16 * 4, OFF_DB2 * 4, cudaMemcpyDeviceToDevice);
    cudaMemcpyToSymbolAsync(cWt, d_in[7],  2752 * 4, OFF_CW1 * 4, cudaMemcpyDeviceToDevice);
    cudaMemcpyToSymbolAsync(cWt, d_in[8],    64 * 4, OFF_CB1 * 4, cudaMemcpyDeviceToDevice);
    cudaMemcpyToSymbolAsync(cWt, d_in[9],  4096 * 4, OFF_CW2 * 4, cudaMemcpyDeviceToDevice);
    cudaMemcpyToSymbolAsync(cWt, d_in[10],   64 * 4, OFF_CB2 * 4, cudaMemcpyDeviceToDevice);
    cudaMemcpyToSymbolAsync(cWt, d_in[11],  192 * 4, OFF_CW3 * 4, cudaMemcpyDeviceToDevice);
    cudaMemcpyToSymbolAsync(cWt, d_in[12],    3 * 4, OFF_CB3 * 4, cudaMemcpyDeviceToDevice);

    const int P = in_sizes[0] / 3;          // 393216 = 64 * 6144

    ngp_gather_kernel<<<(P + 255) / 256, 256>>>(x, tables, P);
    ngp_mlp_kernel<<<P / PTS_PER_BLOCK, 128>>>(x, rdir, out, P);
}

// round 15
// speedup vs baseline: 3.5508x; 3.5508x over previous
#include <cuda_runtime.h>

// -------- Instant-NGP constants --------
#define NLEV 16
#define TSZ  (1u << 19)
#define HMASK (TSZ - 1u)
#define P2 2654435761u
#define P3 805459861u

#define PMAX 393216                 // 2048 * 192 (fixed problem shape)

// scratch: feats laid out as [chunk 0..7][point][float4] — coalesced both ways
__device__ float4 g_feats[8 * PMAX];

// ---- weights in the constant bank: immediate-addressed uniform loads ----
#define OFF_DW1 0      // 32*64 = 2048
#define OFF_DB1 2048   // 64
#define OFF_DW2 2112   // 64*16 = 1024
#define OFF_DB2 3136   // 16
#define OFF_CW1 3152   // 43*64 = 2752
#define OFF_CB1 5904   // 64
#define OFF_CW2 5968   // 64*64 = 4096
#define OFF_CB2 10064  // 64
#define OFF_CW3 10128  // 64*3 = 192
#define OFF_CB3 10320  // 3
#define W_PAD   10324  // 41,296 bytes < 64KB constant bank

__constant__ __align__(16) float cWt[W_PAD];

// ---- packed f32x2 helpers (sm_103a FFMA2 — PTX-only) ----
typedef unsigned long long u64t;
__device__ __forceinline__ void ffma2(u64t& d, u64t a2, u64t b2) {
    asm("fma.rn.f32x2 %0, %1, %2, %0;" : "+l"(d) : "l"(a2), "l"(b2));
}
__device__ __forceinline__ u64t dup2(float a) {
    u64t r; unsigned ai = __float_as_uint(a);
    asm("mov.b64 %0, {%1, %1};" : "=l"(r) : "r"(ai));
    return r;
}
__device__ __forceinline__ void unpack2(u64t v, float& lo, float& hi) {
    unsigned l, h;
    asm("mov.b64 {%0, %1}, %2;" : "=r"(l), "=r"(h) : "l"(v));
    lo = __uint_as_float(l); hi = __uint_as_float(h);
}

// ============================ Kernel A: hash gather ============================
__global__ void __launch_bounds__(256)
ngp_gather_kernel(const float* __restrict__ x,
                  const float* __restrict__ tables, int P)
{
    const int p = blockIdx.x * 256 + threadIdx.x;
    if (p >= P) return;

    const float xf0 = x[3 * p + 0] + 0.5f;
    const float xf1 = x[3 * p + 1] + 0.5f;
    const float xf2 = x[3 * p + 2] + 0.5f;
    const bool inside = (xf0 > 0.f) & (xf0 < 1.f) &
                        (xf1 > 0.f) & (xf1 < 1.f) &
                        (xf2 > 0.f) & (xf2 < 1.f);
    if (!inside) {
        const float4 z = make_float4(0.f, 0.f, 0.f, 0.f);
#pragma unroll
        for (int c = 0; c < 8; c++) g_feats[c * PMAX + p] = z;
        return;
    }

    const float LVL[NLEV] = {16.f, 22.f, 30.f, 42.f, 58.f, 80.f, 111.f, 153.f,
                             212.f, 294.f, 406.f, 561.f, 776.f, 1072.f, 1482.f, 2048.f};
    const float2* __restrict__ tab2 = (const float2*)tables;

    float prevx = 0.f, prevy = 0.f;
#pragma unroll
    for (int l = 0; l < NLEV; l++) {
        const float R = LVL[l];
        const float px = xf0 * R, py = xf1 * R, pz = xf2 * R;
        const float fx = floorf(px), fy = floorf(py), fz = floorf(pz);
        const float frx = px - fx, fry = py - fy, frz = pz - fz;
        const unsigned ux0 = (unsigned)(int)fx;
        const unsigned ux1 = (unsigned)(int)ceilf(px);
        const unsigned uy0 = (unsigned)(int)fy        * P2;
        const unsigned uy1 = (unsigned)(int)ceilf(py) * P2;
        const unsigned uz0 = (unsigned)(int)fz        * P3;
        const unsigned uz1 = (unsigned)(int)ceilf(pz) * P3;
        const float wx0 = 1.f - frx, wy0 = 1.f - fry, wz0 = 1.f - frz;
        const float2* __restrict__ tl = tab2 + (size_t)l * TSZ;
        float ax = 0.f, ay = 0.f;
#pragma unroll
        for (int c = 0; c < 8; c++) {
            unsigned h = ((c & 1) ? ux1 : ux0) ^ ((c & 2) ? uy1 : uy0) ^
                         ((c & 4) ? uz1 : uz0);
            h &= HMASK;
            const float2 v = __ldg(&tl[h]);
            const float w = ((c & 1) ? frx : wx0) * ((c & 2) ? fry : wy0) *
                            ((c & 4) ? frz : wz0);
            ax = fmaf(w, v.x, ax);
            ay = fmaf(w, v.y, ay);
        }
        if (l & 1) {
            g_feats[(l >> 1) * PMAX + p] = make_float4(prevx, prevy, ax, ay);
        } else {
            prevx = ax; prevy = ay;
        }
    }
}

// ============================ Kernel B: fused MLPs (f32x2 + const weights, reg-trimmed) ============================
__global__ void __launch_bounds__(128, 5)
ngp_mlp_kernel(const float* __restrict__ x,
               const float* __restrict__ rdir,
               float* __restrict__ out, int P)
{
    const int tid = threadIdx.x;
    const int p = blockIdx.x * 128 + tid;
    if (p >= P) return;

    const float xf0 = x[3 * p + 0] + 0.5f;
    const float xf1 = x[3 * p + 1] + 0.5f;
    const float xf2 = x[3 * p + 2] + 0.5f;
    const bool inside = (xf0 > 0.f) & (xf0 < 1.f) &
                        (xf1 > 0.f) & (xf1 < 1.f) &
                        (xf2 > 0.f) & (xf2 < 1.f);

    // ---- density layer 1: acc2[32] (pairs of outputs) = feats @ dW1 + db1 ----
    u64t acc2[32];
    {
        const u64t* __restrict__ b = (const u64t*)(cWt + OFF_DB1);
#pragma unroll
        for (int j = 0; j < 32; j++) acc2[j] = b[j];
    }
#pragma unroll
    for (int c = 0; c < 8; c++) {
        const float4 f = __ldg(&g_feats[c * PMAX + p]);
        const float fa[4] = {f.x, f.y, f.z, f.w};
#pragma unroll
        for (int i = 0; i < 4; i++) {
            const u64t a2 = dup2(fa[i]);
            const u64t* __restrict__ w = (const u64t*)(cWt + OFF_DW1 + (4 * c + i) * 64);
#pragma unroll
            for (int j = 0; j < 32; j++) ffma2(acc2[j], a2, w[j]);
        }
    }
    float h1[64];
#pragma unroll
    for (int j = 0; j < 32; j++) {
        float lo, hi; unpack2(acc2[j], lo, hi);
        h1[2 * j + 0] = fmaxf(lo, 0.f);
        h1[2 * j + 1] = fmaxf(hi, 0.f);
    }

    // ---- density layer 2: ls[16] = h1 @ dW2 + db2 (packed pairs) ----
    u64t lsa[8];
    {
        const u64t* __restrict__ b = (const u64t*)(cWt + OFF_DB2);
#pragma unroll
        for (int j = 0; j < 8; j++) lsa[j] = b[j];
    }
#pragma unroll
    for (int k = 0; k < 64; k++) {
        const u64t a2 = dup2(h1[k]);
        const u64t* __restrict__ w = (const u64t*)(cWt + OFF_DW2 + k * 16);
#pragma unroll
        for (int j = 0; j < 8; j++) ffma2(lsa[j], a2, w[j]);
    }
    float ls[16];
#pragma unroll
    for (int j = 0; j < 8; j++) unpack2(lsa[j], ls[2 * j], ls[2 * j + 1]);
    const float ls0 = ls[0];

    // ---- color layer 1, sweep 1: consume ls[16] (rows 0..15 of cW1), then ls dies ----
    {
        const u64t* __restrict__ b = (const u64t*)(cWt + OFF_CB1);
#pragma unroll
        for (int j = 0; j < 32; j++) acc2[j] = b[j];
    }
#pragma unroll
    for (int k = 0; k < 16; k++) {
        const u64t a2 = dup2(ls[k]);
        const u64t* __restrict__ w = (const u64t*)(cWt + OFF_CW1 + k * 64);
#pragma unroll
        for (int j = 0; j < 32; j++) ffma2(acc2[j], a2, w[j]);
    }

    // ---- direction PE (born only after ls is dead — keeps peak live-set low) ----
    float pe[27];
    {
        const float r0 = rdir[3 * p + 0];
        const float r1 = rdir[3 * p + 1];
        const float r2 = rdir[3 * p + 2];
        pe[0] = r0; pe[1] = r1; pe[2] = r2;
        const float rv[3] = {r0, r1, r2};
#pragma unroll
        for (int d = 0; d < 3; d++) {
#pragma unroll
            for (int l = 0; l < 4; l++) {
                float s, c;
                __sincosf(rv[d] * (6.283185307179586f * (float)(1 << l)), &s, &c);
                pe[3 + d * 8 + l]     = s;
                pe[3 + d * 8 + 4 + l] = c;
            }
        }
    }

    // ---- color layer 1, sweep 2: consume pe[27] (rows 16..42 of cW1) ----
#pragma unroll
    for (int k = 16; k < 43; k++) {
        const u64t a2 = dup2(pe[k - 16]);
        const u64t* __restrict__ w = (const u64t*)(cWt + OFF_CW1 + k * 64);
#pragma unroll
        for (int j = 0; j < 32; j++) ffma2(acc2[j], a2, w[j]);
    }
    float h[64];
#pragma unroll
    for (int j = 0; j < 32; j++) {
        float lo, hi; unpack2(acc2[j], lo, hi);
        h[2 * j + 0] = fmaxf(lo, 0.f);
        h[2 * j + 1] = fmaxf(hi, 0.f);
    }

    // ---- color layers 2+3 fused, j-blocked by 32 outputs (16 pairs) ----
    float c0 = cWt[OFF_CB3 + 0], c1 = cWt[OFF_CB3 + 1], c2 = cWt[OFF_CB3 + 2];
#pragma unroll
    for (int jb = 0; jb < 2; jb++) {
        u64t a2b[16];
        {
            const u64t* __restrict__ b = (const u64t*)(cWt + OFF_CB2 + jb * 32);
#pragma unroll
            for (int j = 0; j < 16; j++) a2b[j] = b[j];
        }
#pragma unroll
        for (int k = 0; k < 64; k++) {
            const u64t a2 = dup2(h[k]);
            const u64t* __restrict__ w = (const u64t*)(cWt + OFF_CW2 + k * 64 + jb * 32);
#pragma unroll
            for (int j = 0; j < 16; j++) ffma2(a2b[j], a2, w[j]);
        }
#pragma unroll
        for (int j = 0; j < 16; j++) {
            float lo, hi; unpack2(a2b[j], lo, hi);
            const float v0 = fmaxf(lo, 0.f);
            const float v1 = fmaxf(hi, 0.f);
            const int idx = jb * 32 + 2 * j;
            c0 = fmaf(v0, cWt[OFF_CW3 + idx * 3 + 0], c0);
            c1 = fmaf(v0, cWt[OFF_CW3 + idx * 3 + 1], c1);
            c2 = fmaf(v0, cWt[OFF_CW3 + idx * 3 + 2], c2);
            c0 = fmaf(v1, cWt[OFF_CW3 + idx * 3 + 3], c0);
            c1 = fmaf(v1, cWt[OFF_CW3 + idx * 3 + 4], c1);
            c2 = fmaf(v1, cWt[OFF_CW3 + idx * 3 + 5], c2);
        }
    }

    float o0 = 1.f / (1.f + __expf(-c0));
    float o1 = 1.f / (1.f + __expf(-c1));
    float o2 = 1.f / (1.f + __expf(-c2));
    float sg = __expf(ls0);
    if (!inside) { o0 = 0.f; o1 = 0.f; o2 = 0.f; sg = 0.f; }

    out[3 * p + 0] = o0;
    out[3 * p + 1] = o1;
    out[3 * p + 2] = o2;
    out[3 * P + p] = sg;
}

extern "C" void kernel_launch(void* const* d_in, const int* in_sizes, int n_in,
                              void* d_out, int out_size)
{
    (void)n_in; (void)out_size;
    const float* x      = (const float*)d_in[0];
    const float* rdir   = (const float*)d_in[1];
    const float* tables = (const float*)d_in[2];
    float* out = (float*)d_out;

    // weights -> constant bank (device-to-device async copies: graph-capturable)
    cudaMemcpyToSymbolAsync(cWt, d_in[3],  2048 * 4, OFF_DW1 * 4, cudaMemcpyDeviceToDevice);
    cudaMemcpyToSymbolAsync(cWt, d_in[4],    64 * 4, OFF_DB1 * 4, cudaMemcpyDeviceToDevice);
    cudaMemcpyToSymbolAsync(cWt, d_in[5],  1024 * 4, OFF_DW2 * 4, cudaMemcpyDeviceToDevice);
    cudaMemcpyToSymbolAsync(cWt, d_in[6],    16 * 4, OFF_DB2 * 4, cudaMemcpyDeviceToDevice);
    cudaMemcpyToSymbolAsync(cWt, d_in[7],  2752 * 4, OFF_CW1 * 4, cudaMemcpyDeviceToDevice);
    cudaMemcpyToSymbolAsync(cWt, d_in[8],    64 * 4, OFF_CB1 * 4, cudaMemcpyDeviceToDevice);
    cudaMemcpyToSymbolAsync(cWt, d_in[9],  4096 * 4, OFF_CW2 * 4, cudaMemcpyDeviceToDevice);
    cudaMemcpyToSymbolAsync(cWt, d_in[10],   64 * 4, OFF_CB2 * 4, cudaMemcpyDeviceToDevice);
    cudaMemcpyToSymbolAsync(cWt, d_in[11],  192 * 4, OFF_CW3 * 4, cudaMemcpyDeviceToDevice);
    cudaMemcpyToSymbolAsync(cWt, d_in[12],    3 * 4, OFF_CB3 * 4, cudaMemcpyDeviceToDevice);

    const int P = in_sizes[0] / 3;          // 393216

    ngp_gather_kernel<<<(P + 255) / 256, 256>>>(x, tables, P);
    ngp_mlp_kernel<<<(P + 127) / 128, 128>>>(x, rdir, out, P);
}